// round 3
// baseline (speedup 1.0000x reference)
#include <cuda_runtime.h>

#define BATCH 524288
#define TPB 128
typedef unsigned long long u64;

// ---- packed f32x2 primitives ----
#define F2MUL(d,a,b)    asm("mul.rn.f32x2 %0, %1, %2;" : "=l"(d) : "l"(a), "l"(b))
#define F2ADD(d,a,b)    asm("add.rn.f32x2 %0, %1, %2;" : "=l"(d) : "l"(a), "l"(b))
#define F2FMA(d,a,b,c)  asm("fma.rn.f32x2 %0, %1, %2, %3;" : "=l"(d) : "l"(a), "l"(b), "l"(c))
#define F2PACK(d,lo,hi) asm("mov.b64 %0, {%1, %2};" : "=l"(d) : "f"(lo), "f"(hi))
#define F2UNPACK(lo,hi,s) asm("mov.b64 {%0, %1}, %2;" : "=f"(lo), "=f"(hi) : "l"(s))
#define F2SWAP(d,s) asm("{\n\t.reg .b32 _l,_h;\n\tmov.b64 {_l,_h}, %1;\n\tmov.b64 %0, {_h,_l};\n\t}" : "=l"(d) : "l"(s))

__device__ __forceinline__ float2 cmul(float2 a, float2 b) {
    return make_float2(fmaf(a.x, b.x, -a.y * b.y), fmaf(a.x, b.y, a.y * b.x));
}

// RZ on one pack: Re' = sv*Im + cz*Re ; Im' = nsv*Re + cz*Im
__device__ __forceinline__ void rz2(u64& Re, u64& Im, u64 c2, u64 sv, u64 nsv) {
    u64 tr, ti, oR = Re;
    F2MUL(tr, c2, Re); F2MUL(ti, c2, Im);
    F2FMA(Re, sv, Im, tr);
    F2FMA(Im, nsv, oR, ti);
}

// RY on a lane-aligned pack pair: A' = cy*A + sA*B ; B' = cy*B + sB*A
__device__ __forceinline__ void ry2(u64& AR, u64& AI, u64& BR, u64& BI,
                                    u64 c2, u64 sA, u64 sB) {
    u64 t1, t2, t3, t4, oAR = AR, oAI = AI;
    F2MUL(t1, c2, AR); F2MUL(t2, c2, AI); F2MUL(t3, c2, BR); F2MUL(t4, c2, BI);
    F2FMA(AR, sA, BR, t1);
    F2FMA(AI, sA, BI, t2);
    F2FMA(BR, sB, oAR, t3);
    F2FMA(BI, sB, oAI, t4);
}

// RY on qubit 3 (cross-lane): X' = cy*X + sA*swap(partner)
__device__ __forceinline__ void ry2x(u64& AR, u64& AI, u64& BR, u64& BI,
                                     u64 c2, u64 sA) {
    u64 wBR, wBI, wAR, wAI, t1, t2, t3, t4;
    F2SWAP(wBR, BR); F2SWAP(wBI, BI); F2SWAP(wAR, AR); F2SWAP(wAI, AI);
    F2MUL(t1, c2, AR); F2MUL(t2, c2, AI); F2MUL(t3, c2, BR); F2MUL(t4, c2, BI);
    F2FMA(AR, sA, wBR, t1);
    F2FMA(AI, sA, wBI, t2);
    F2FMA(BR, sA, wAR, t3);
    F2FMA(BI, sA, wAI, t4);
}

__global__ void __launch_bounds__(TPB) quantum_layer_kernel(
    const float4* __restrict__ x, const float* __restrict__ w,
    float4* __restrict__ out)
{
    // layer-0 scalar half-angle trig + layer-1 prepacked f32x2 constants
    __shared__ float tcs[8], tss[8];
    __shared__ float2 s_cz2[4], s_szA[4], s_szB[4], s_cy2[4], s_syA[4], s_syB[4];
    int tid = threadIdx.x;
    if (tid < 8) {
        float a = 0.5f * w[tid];
        float s, c; sincosf(a, &s, &c);
        tcs[tid] = c; tss[tid] = s;
    } else if (tid < 12) {
        int q = tid - 8;
        float sz, cz, sy, cy;
        sincosf(0.5f * w[8 + 2 * q], &sz, &cz);
        sincosf(0.5f * w[9 + 2 * q], &sy, &cy);
        float zh = (q == 2) ? sz : -sz;     // hi-lane sign of the RZ sine pack
        float yh = (q == 2) ? -sy : sy;     // hi-lane sign of the RY sine pack
        s_cz2[q] = make_float2(cz, cz);
        s_szA[q] = make_float2(sz, zh);
        s_szB[q] = make_float2(-sz, -zh);
        s_cy2[q] = make_float2(cy, cy);
        s_syA[q] = make_float2(-sy, yh);
        s_syB[q] = make_float2(sy, -yh);
    }
    __syncthreads();

    unsigned b = blockIdx.x * (unsigned)TPB + tid;
    float4 xv = x[b];
    float xs[4] = {xv.x, xv.y, xv.z, xv.w};

    // ---- product-state prologue: input RY + layer-0 RZ,RY on 2-vectors ----
    float2 u0[4], u1[4];
    #pragma unroll
    for (int q = 0; q < 4; q++) {
        float sx, cx;
        __sincosf(0.5f * xs[q], &sx, &cx);
        float cz = tcs[2 * q], sz = tss[2 * q];
        float cy = tcs[2 * q + 1], sy = tss[2 * q + 1];
        float2 v0 = make_float2(cx * cz, -cx * sz);
        float2 v1 = make_float2(sx * cz,  sx * sz);
        u0[q] = make_float2(fmaf(cy, v0.x, -sy * v1.x), fmaf(cy, v0.y, -sy * v1.y));
        u1[q] = make_float2(fmaf(sy, v0.x,  cy * v1.x), fmaf(sy, v0.y,  cy * v1.y));
    }

    float2 a01[4], a23[4];
    a01[0] = cmul(u0[0], u0[1]); a01[1] = cmul(u0[0], u1[1]);
    a01[2] = cmul(u1[0], u0[1]); a01[3] = cmul(u1[0], u1[1]);
    a23[0] = cmul(u0[2], u0[3]); a23[1] = cmul(u0[2], u1[3]);
    a23[2] = cmul(u1[2], u0[3]); a23[3] = cmul(u1[2], u1[3]);

    // ---- packed operands for the tensor product (packing along amp-mask 7,
    //      which the first CNOT ring maps to st-mask 13 for free) ----
    u64 A01x, A01y, nA01y, A10x, A10y, nA10y;
    u64 A23x, A23y, nA23y, A32x, A32y, nA32y;
    F2PACK(A01x, a01[0].x, a01[1].x); F2PACK(A01y, a01[0].y, a01[1].y);
    F2PACK(nA01y, -a01[0].y, -a01[1].y);
    F2PACK(A10x, a01[1].x, a01[0].x); F2PACK(A10y, a01[1].y, a01[0].y);
    F2PACK(nA10y, -a01[1].y, -a01[0].y);
    F2PACK(A23x, a01[2].x, a01[3].x); F2PACK(A23y, a01[2].y, a01[3].y);
    F2PACK(nA23y, -a01[2].y, -a01[3].y);
    F2PACK(A32x, a01[3].x, a01[2].x); F2PACK(A32y, a01[3].y, a01[2].y);
    F2PACK(nA32y, -a01[3].y, -a01[2].y);

    u64 Q03x, Q03y, Q30x, Q30y, Q21x, Q21y, Q12x, Q12y;
    F2PACK(Q03x, a23[0].x, a23[3].x); F2PACK(Q03y, a23[0].y, a23[3].y);
    F2PACK(Q30x, a23[3].x, a23[0].x); F2PACK(Q30y, a23[3].y, a23[0].y);
    F2PACK(Q21x, a23[2].x, a23[1].x); F2PACK(Q21y, a23[2].y, a23[1].y);
    F2PACK(Q12x, a23[1].x, a23[2].x); F2PACK(Q12y, a23[1].y, a23[2].y);

    // st pack k: lane0 = st-amp 2k, lane1 = st-amp 2k^13 (state AFTER CNOT ring 1)
    // amp (pre-perm) lanes: k: (0,7)(3,4)(6,1)(5,2)(12,11)(15,8)(10,13)(9,14)
    u64 sR[8], sI[8];
    #define TPROD(k, Ax, Ay, nAy, Qx, Qy) { u64 m; \
        F2MUL(m, Ax, Qx); F2FMA(sR[k], nAy, Qy, m);  \
        F2MUL(m, Ax, Qy); F2FMA(sI[k], Ay, Qx, m); }
    TPROD(0, A01x, A01y, nA01y, Q03x, Q03y)
    TPROD(1, A01x, A01y, nA01y, Q30x, Q30y)
    TPROD(2, A10x, A10y, nA10y, Q21x, Q21y)
    TPROD(3, A10x, A10y, nA10y, Q12x, Q12y)
    TPROD(4, A32x, A32y, nA32y, Q03x, Q03y)
    TPROD(5, A32x, A32y, nA32y, Q30x, Q30y)
    TPROD(6, A23x, A23y, nA23y, Q21x, Q21y)
    TPROD(7, A23x, A23y, nA23y, Q12x, Q12y)

    // ---- layer 1: per qubit RZ then RY, all packed along mask 13 ----
    const u64* czp = reinterpret_cast<const u64*>(s_cz2);
    const u64* zAp = reinterpret_cast<const u64*>(s_szA);
    const u64* zBp = reinterpret_cast<const u64*>(s_szB);
    const u64* cyp = reinterpret_cast<const u64*>(s_cy2);
    const u64* yAp = reinterpret_cast<const u64*>(s_syA);
    const u64* yBp = reinterpret_cast<const u64*>(s_syB);

    // q0: RZ sign by bit0(lane0 amp 2k) = k>>2 ; RY pairs (k, k+4)
    {
        u64 c2 = czp[0], zA = zAp[0], zB = zBp[0];
        #pragma unroll
        for (int k = 0; k < 8; k++) {
            bool s1 = (k >> 2) & 1;
            rz2(sR[k], sI[k], c2, s1 ? zB : zA, s1 ? zA : zB);
        }
        u64 y2 = cyp[0], yA = yAp[0], yB = yBp[0];
        ry2(sR[0], sI[0], sR[4], sI[4], y2, yA, yB);
        ry2(sR[1], sI[1], sR[5], sI[5], y2, yA, yB);
        ry2(sR[2], sI[2], sR[6], sI[6], y2, yA, yB);
        ry2(sR[3], sI[3], sR[7], sI[7], y2, yA, yB);
    }
    // q1: RZ sign by bit1 = (k>>1)&1 ; RY pairs (0,2)(1,3)(4,6)(5,7)
    {
        u64 c2 = czp[1], zA = zAp[1], zB = zBp[1];
        #pragma unroll
        for (int k = 0; k < 8; k++) {
            bool s1 = (k >> 1) & 1;
            rz2(sR[k], sI[k], c2, s1 ? zB : zA, s1 ? zA : zB);
        }
        u64 y2 = cyp[1], yA = yAp[1], yB = yBp[1];
        ry2(sR[0], sI[0], sR[2], sI[2], y2, yA, yB);
        ry2(sR[1], sI[1], sR[3], sI[3], y2, yA, yB);
        ry2(sR[4], sI[4], sR[6], sI[6], y2, yA, yB);
        ry2(sR[5], sI[5], sR[7], sI[7], y2, yA, yB);
    }
    // q2: bit2 shared by lanes = k&1 ; RY pairs (0,1)(2,3)(4,5)(6,7)
    {
        u64 c2 = czp[2], zA = zAp[2], zB = zBp[2];
        #pragma unroll
        for (int k = 0; k < 8; k++) {
            bool s1 = k & 1;
            rz2(sR[k], sI[k], c2, s1 ? zB : zA, s1 ? zA : zB);
        }
        u64 y2 = cyp[2], yA = yAp[2], yB = yBp[2];
        ry2(sR[0], sI[0], sR[1], sI[1], y2, yA, yB);
        ry2(sR[2], sI[2], sR[3], sI[3], y2, yA, yB);
        ry2(sR[4], sI[4], sR[5], sI[5], y2, yA, yB);
        ry2(sR[6], sI[6], sR[7], sI[7], y2, yA, yB);
    }
    // q3: lane0 always bit3=0 ; RY cross-lane, pairs (0,6)(1,7)(2,4)(3,5)
    {
        u64 c2 = czp[3], zA = zAp[3], zB = zBp[3];
        #pragma unroll
        for (int k = 0; k < 8; k++)
            rz2(sR[k], sI[k], c2, zA, zB);
        u64 y2 = cyp[3], yA = yAp[3];
        ry2x(sR[0], sI[0], sR[6], sI[6], y2, yA);
        ry2x(sR[1], sI[1], sR[7], sI[7], y2, yA);
        ry2x(sR[2], sI[2], sR[4], sI[4], y2, yA);
        ry2x(sR[3], sI[3], sR[5], sI[5], y2, yA);
    }

    // ---- readout: second CNOT ring folded into sign tables ----
    // pack k lanes = final amps (f0,f0^1), f0 = [0,11,15,4,7,12,8,3]
    u64 p[8];
    #pragma unroll
    for (int k = 0; k < 8; k++) {
        u64 t;
        F2MUL(t, sR[k], sR[k]);
        F2FMA(p[k], sI[k], sI[k], t);
    }
    u64 NEG1; F2PACK(NEG1, -1.0f, -1.0f);
    u64 a0, a1, a2, a3, d0, d1, d2, d3;
    F2ADD(a0, p[0], p[1]); F2FMA(d0, p[1], NEG1, p[0]);
    F2ADD(a1, p[2], p[3]); F2FMA(d1, p[3], NEG1, p[2]);
    F2ADD(a2, p[4], p[5]); F2FMA(d2, p[5], NEG1, p[4]);
    F2ADD(a3, p[6], p[7]); F2FMA(d3, p[7], NEG1, p[6]);
    u64 t1, t2, M0, M1, M2;
    F2ADD(t1, d0, d2); F2ADD(t2, d1, d3); F2FMA(M0, t2, NEG1, t1);  // <Z0> signs
    F2ADD(t1, a0, a3); F2ADD(t2, a1, a2); F2FMA(M1, t2, NEG1, t1);  // <Z1> signs
    F2ADD(t1, d0, d3); F2ADD(t2, d1, d2); F2FMA(M2, t2, NEG1, t1);  // <Z2>/<Z3>
    float l0, h0, l1, h1, l2, h2;
    F2UNPACK(l0, h0, M0);
    F2UNPACK(l1, h1, M1);
    F2UNPACK(l2, h2, M2);
    float4 o;
    o.x = l0 + h0;
    o.y = l1 + h1;
    o.z = l2 + h2;
    o.w = l2 - h2;
    out[b] = o;
}

extern "C" void kernel_launch(void* const* d_in, const int* in_sizes, int n_in,
                              void* d_out, int out_size) {
    const float4* x = (const float4*)d_in[0];
    const float*  w = (const float*)d_in[1];
    float4* out = (float4*)d_out;
    quantum_layer_kernel<<<BATCH / TPB, TPB>>>(x, w, out);
}

// round 4
// speedup vs baseline: 1.1212x; 1.1212x over previous
#include <cuda_runtime.h>

#define BATCH 524288
#define TPB 256
typedef unsigned long long u64;

// ---- packed f32x2 primitives ----
#define F2MUL(d,a,b)    asm("mul.rn.f32x2 %0, %1, %2;" : "=l"(d) : "l"(a), "l"(b))
#define F2ADD(d,a,b)    asm("add.rn.f32x2 %0, %1, %2;" : "=l"(d) : "l"(a), "l"(b))
#define F2FMA(d,a,b,c)  asm("fma.rn.f32x2 %0, %1, %2, %3;" : "=l"(d) : "l"(a), "l"(b), "l"(c))
#define F2PACK(d,lo,hi) asm("mov.b64 %0, {%1, %2};" : "=l"(d) : "f"(lo), "f"(hi))
#define F2UNPACK(lo,hi,s) asm("mov.b64 {%0, %1}, %2;" : "=f"(lo), "=f"(hi) : "l"(s))
#define F2SWAP(d,s) asm("{\n\t.reg .b32 _l,_h;\n\tmov.b64 {_l,_h}, %1;\n\tmov.b64 %0, {_h,_l};\n\t}" : "=l"(d) : "l"(s))

__device__ __forceinline__ float2 cmul(float2 a, float2 b) {
    return make_float2(fmaf(a.x, b.x, -a.y * b.y), fmaf(a.x, b.y, a.y * b.x));
}

// lane-aligned RY on pack pair: A' = c*A + sA*B ; B' = c*B + sB*oldA
__device__ __forceinline__ void ry_al(u64& AR, u64& AI, u64& BR, u64& BI,
                                      u64 c2, u64 sA, u64 sB) {
    u64 t1, t2, t3, t4, oAR = AR, oAI = AI;
    F2MUL(t1, c2, AR); F2MUL(t2, c2, AI); F2MUL(t3, c2, BR); F2MUL(t4, c2, BI);
    F2FMA(AR, sA, BR, t1);
    F2FMA(AI, sA, BI, t2);
    F2FMA(BR, sB, oAR, t3);
    F2FMA(BI, sB, oAI, t4);
}

__global__ void __launch_bounds__(TPB) quantum_layer_kernel(
    const float4* __restrict__ x, const float* __restrict__ w,
    float4* __restrict__ out)
{
    __shared__ float tcs[8], tss[8];                       // layer-0 half-angle trig
    __shared__ __align__(8) float dC[16], dI[16], dnI[16]; // fused RZ diagonal (packed layout)
    __shared__ float2 r0c[3], r1c[3], r2c[3];              // RY consts wires 0,1,2
    __shared__ float w3c[2];                               // cos(w3), -2 sin(w3)

    int tid = threadIdx.x;
    if (tid < 8) {
        float s, c; sincosf(0.5f * w[tid], &s, &c);
        tcs[tid] = c; tss[tid] = s;
    } else if (tid >= 16 && tid < 32) {
        // diagonal: phi(k) = sum_q (w[8+2q]/2) * (-1)^par(k & m_q), m = {7,12,14,15}
        int k = tid - 16;
        float phi = 0.5f * ( w[8]  * ((__popc(k & 7)  & 1) ? -1.f : 1.f)
                           + w[10] * ((__popc(k & 12) & 1) ? -1.f : 1.f)
                           + w[12] * ((__popc(k & 14) & 1) ? -1.f : 1.f)
                           + w[14] * ((__popc(k & 15) & 1) ? -1.f : 1.f) );
        float sp, cp; sincosf(phi, &sp, &cp);
        int pos = (k < 8) ? 2 * k : 2 * (k ^ 12) + 1;  // pack p = k or k^12, lane by k0
        dC[pos] = cp; dI[pos] = -sp; dnI[pos] = sp;    // e^{-i phi} = (cp, -sp)
    } else if (tid == 32) {       // wire0 RY, angle w[9]; in-pack cross-lane signs
        float s, c; sincosf(0.5f * w[9], &s, &c);
        r0c[0] = make_float2(c, c); r0c[1] = make_float2(-s, s); r0c[2] = make_float2(s, -s);
    } else if (tid == 33) {       // wire1 RY, angle w[11]
        float s, c; sincosf(0.5f * w[11], &s, &c);
        r1c[0] = make_float2(c, c); r1c[1] = make_float2(-s, -s); r1c[2] = make_float2(s, s);
    } else if (tid == 34) {       // wire2 RY, angle w[13]
        float s, c; sincosf(0.5f * w[13], &s, &c);
        r2c[0] = make_float2(c, c); r2c[1] = make_float2(-s, -s); r2c[2] = make_float2(s, s);
    } else if (tid == 35) {       // wire3 RY fused into readout: full angle w[15]
        float s, c; sincosf(w[15], &s, &c);
        w3c[0] = c; w3c[1] = -2.f * s;
    }
    __syncthreads();

    unsigned b = blockIdx.x * (unsigned)TPB + tid;
    float4 xv = x[b];
    float xs[4] = {xv.x, xv.y, xv.z, xv.w};

    // ---- product-state prologue: input RY + layer-0 RZ,RY on 2-vectors ----
    float2 u0[4], u1[4];
    #pragma unroll
    for (int q = 0; q < 4; q++) {
        float sx, cx;
        __sincosf(0.5f * xs[q], &sx, &cx);
        float cz = tcs[2 * q], sz = tss[2 * q];
        float cy = tcs[2 * q + 1], sy = tss[2 * q + 1];
        float2 v0 = make_float2(cx * cz, -cx * sz);
        float2 v1 = make_float2(sx * cz,  sx * sz);
        u0[q] = make_float2(fmaf(cy, v0.x, -sy * v1.x), fmaf(cy, v0.y, -sy * v1.y));
        u1[q] = make_float2(fmaf(sy, v0.x,  cy * v1.x), fmaf(sy, v0.y,  cy * v1.y));
    }
    float2 a01[4], a23[4];
    a01[0] = cmul(u0[0], u0[1]); a01[1] = cmul(u0[0], u1[1]);
    a01[2] = cmul(u1[0], u0[1]); a01[3] = cmul(u1[0], u1[1]);
    a23[0] = cmul(u0[2], u0[3]); a23[1] = cmul(u0[2], u1[3]);
    a23[2] = cmul(u1[2], u0[3]); a23[3] = cmul(u1[2], u1[3]);

    // ---- tensor product straight into packs along mask 12:
    //      pack p (p<8): lane0 = amp(k=p) = a01[p>>2]*a23[p&3], lane1 = amp(p^12) ----
    u64 A0R, A0I, A1R, A1I;
    F2PACK(A0R, a01[0].x, a01[3].x); F2PACK(A0I, a01[0].y, a01[3].y);
    F2PACK(A1R, a01[1].x, a01[2].x); F2PACK(A1I, a01[1].y, a01[2].y);
    u64 sR[8], sI[8];
    #pragma unroll
    for (int j = 0; j < 4; j++) {
        u64 BR, BI, nBI, t;
        F2PACK(BR, a23[j].x, a23[j].x);
        F2PACK(BI, a23[j].y, a23[j].y);
        float nb = -a23[j].y;
        F2PACK(nBI, nb, nb);
        F2MUL(t, A0R, BR); F2FMA(sR[j],     A0I, nBI, t);
        F2MUL(t, A0R, BI); F2FMA(sI[j],     A0I, BR,  t);
        F2MUL(t, A1R, BR); F2FMA(sR[4 + j], A1I, nBI, t);
        F2MUL(t, A1R, BI); F2FMA(sI[4 + j], A1I, BR,  t);
    }

    // ---- fused layer-1 RZ diagonal (all 4 qubits at once) ----
    {
        const u64* dCp  = reinterpret_cast<const u64*>(dC);
        const u64* dIp  = reinterpret_cast<const u64*>(dI);
        const u64* dnIp = reinterpret_cast<const u64*>(dnI);
        #pragma unroll
        for (int p = 0; p < 8; p++) {
            u64 cR = dCp[p], cI = dIp[p], ncI = dnIp[p];
            u64 t1, t2, oR = sR[p];
            F2MUL(t1, cR, sR[p]); F2MUL(t2, cR, sI[p]);
            F2FMA(sR[p], ncI, sI[p], t1);   // Re' = cR*Re - cI*Im
            F2FMA(sI[p], cI,  oR,    t2);   // Im' = cR*Im + cI*Re
        }
    }

    // ---- wire0 RY (pair mask 12 = in-pack cross-lane; role = par(p)) ----
    {
        const u64* rc = reinterpret_cast<const u64*>(r0c);
        u64 c0 = rc[0], svE = rc[1], svO = rc[2];
        #pragma unroll
        for (int p = 0; p < 8; p++) {
            u64 sv = (p == 0 || p == 3 || p == 5 || p == 6) ? svE : svO;
            u64 wR, wI, t1, t2;
            F2SWAP(wR, sR[p]); F2SWAP(wI, sI[p]);
            F2MUL(t1, c0, sR[p]); F2MUL(t2, c0, sI[p]);
            F2FMA(sR[p], sv, wR, t1);
            F2FMA(sI[p], sv, wI, t2);
        }
    }
    // ---- wire1 RY (pair mask 6): (A,B) pack pairs (0,6)(1,7)(2,4)(3,5) ----
    {
        const u64* rc = reinterpret_cast<const u64*>(r1c);
        u64 c = rc[0], sA = rc[1], sB = rc[2];
        ry_al(sR[0], sI[0], sR[6], sI[6], c, sA, sB);
        ry_al(sR[1], sI[1], sR[7], sI[7], c, sA, sB);
        ry_al(sR[2], sI[2], sR[4], sI[4], c, sA, sB);
        ry_al(sR[3], sI[3], sR[5], sI[5], c, sA, sB);
    }
    // ---- wire2 RY (pair mask 3): (A,B) pack pairs (0,3)(1,2)(7,4)(6,5) ----
    {
        const u64* rc = reinterpret_cast<const u64*>(r2c);
        u64 c = rc[0], sA = rc[1], sB = rc[2];
        ry_al(sR[0], sI[0], sR[3], sI[3], c, sA, sB);
        ry_al(sR[1], sI[1], sR[2], sI[2], c, sA, sB);
        ry_al(sR[7], sI[7], sR[4], sI[4], c, sA, sB);
        ry_al(sR[6], sI[6], sR[5], sI[5], c, sA, sB);
    }

    // ---- readout with wire3 RY fused ----
    // pre-RY3 probs per pack
    u64 P[8];
    #pragma unroll
    for (int p = 0; p < 8; p++) {
        u64 t; F2MUL(t, sR[p], sR[p]); F2FMA(P[p], sI[p], sI[p], t);
    }
    // cross terms Re(psi_k * conj(psi_{k^13})): pack pairs (0,1)(2,3)(4,5)(6,7), cross-lane
    u64 CR[4];
    #pragma unroll
    for (int i = 0; i < 4; i++) {
        int p = 2 * i;
        u64 wr, wi, t;
        F2SWAP(wr, sR[p + 1]); F2SWAP(wi, sI[p + 1]);
        F2MUL(t, sR[p], wr); F2FMA(CR[i], sI[p], wi, t);
    }
    u64 NEG1; F2PACK(NEG1, -1.0f, -1.0f);
    // butterflies over pack probs
    u64 sm[4], df[4];
    #pragma unroll
    for (int i = 0; i < 4; i++) {
        F2ADD(sm[i], P[2 * i], P[2 * i + 1]);
        F2FMA(df[i], P[2 * i + 1], NEG1, P[2 * i]);
    }
    u64 t1, t2, Ea, Eb, Ec, Up, Vd, g1, g2;
    F2ADD(t1, df[0], df[1]); F2ADD(t2, df[2], df[3]); F2FMA(Ea, t2, NEG1, t1); // sign par(p&5)
    F2ADD(t1, df[0], df[2]); F2ADD(t2, df[1], df[3]); F2FMA(Eb, t2, NEG1, t1); // sign par(p&3)
    F2ADD(t1, sm[0], sm[2]); F2ADD(t2, sm[1], sm[3]); F2FMA(Ec, t2, NEG1, t1); // sign par(p&2)
    F2FMA(g1, CR[1], NEG1, CR[0]); F2FMA(g2, CR[3], NEG1, CR[2]); F2ADD(Up, g1, g2);
    F2ADD(t1, CR[0], CR[1]); F2ADD(t2, CR[2], CR[3]); F2FMA(Vd, t2, NEG1, t1);

    float eal, eah, ebl, ebh, ecl, ech, upl, uph, vdl, vdh;
    F2UNPACK(eal, eah, Ea); F2UNPACK(ebl, ebh, Eb); F2UNPACK(ecl, ech, Ec);
    F2UNPACK(upl, uph, Up); F2UNPACK(vdl, vdh, Vd);
    float c3 = w3c[0], s3n2 = w3c[1];
    float W13 = eal + eah;   // <Z0> prob part (mask 13: lane-sum)
    float W5  = eal - eah;   // <Z2>           (mask 5 : lane-diff, same pack signs)
    float W11 = ebl - ebh;   // <Z1>           (mask 11)
    float W10 = ecl - ech;   // <Z3> prob part (mask 10)
    float C0 = upl + uph;    // cross sum for Z0
    float C3 = vdl - vdh;    // cross sum for Z3
    float4 o;
    o.x = fmaf(c3, W13, s3n2 * C0);
    o.y = W11;
    o.z = W5;
    o.w = fmaf(c3, W10, s3n2 * C3);
    out[b] = o;
}

extern "C" void kernel_launch(void* const* d_in, const int* in_sizes, int n_in,
                              void* d_out, int out_size) {
    const float4* x = (const float4*)d_in[0];
    const float*  w = (const float*)d_in[1];
    float4* out = (float4*)d_out;
    quantum_layer_kernel<<<BATCH / TPB, TPB>>>(x, w, out);
}

// round 5
// speedup vs baseline: 1.2569x; 1.1210x over previous
#include <cuda_runtime.h>

#define BATCH 524288
#define TPB 256
typedef unsigned long long u64;

// ---- packed f32x2 primitives ----
#define F2MUL(d,a,b)    asm("mul.rn.f32x2 %0, %1, %2;" : "=l"(d) : "l"(a), "l"(b))
#define F2ADD(d,a,b)    asm("add.rn.f32x2 %0, %1, %2;" : "=l"(d) : "l"(a), "l"(b))
#define F2FMA(d,a,b,c)  asm("fma.rn.f32x2 %0, %1, %2, %3;" : "=l"(d) : "l"(a), "l"(b), "l"(c))
#define F2PACK(d,lo,hi) asm("mov.b64 %0, {%1, %2};" : "=l"(d) : "f"(lo), "f"(hi))
#define F2UNPACK(lo,hi,s) asm("mov.b64 {%0, %1}, %2;" : "=f"(lo), "=f"(hi) : "l"(s))
#define F2SWAP(d,s) asm("{\n\t.reg .b32 _l,_h;\n\tmov.b64 {_l,_h}, %1;\n\tmov.b64 %0, {_h,_l};\n\t}" : "=l"(d) : "l"(s))

__device__ __forceinline__ float2 cmul(float2 a, float2 b) {
    return make_float2(fmaf(a.x, b.x, -a.y * b.y), fmaf(a.x, b.y, a.y * b.x));
}

// lane-aligned RY on pack pair: A' = c*A + sA*B ; B' = c*B + sB*oldA
__device__ __forceinline__ void ry_al(u64& AR, u64& AI, u64& BR, u64& BI,
                                      u64 c2, u64 sA, u64 sB) {
    u64 t1, t2, t3, t4, oAR = AR, oAI = AI;
    F2MUL(t1, c2, AR); F2MUL(t2, c2, AI); F2MUL(t3, c2, BR); F2MUL(t4, c2, BI);
    F2FMA(AR, sA, BR, t1);
    F2FMA(AI, sA, BI, t2);
    F2FMA(BR, sB, oAR, t3);
    F2FMA(BI, sB, oAI, t4);
}

__global__ void __launch_bounds__(TPB, 5) quantum_layer_kernel(
    const float4* __restrict__ x, const float* __restrict__ w,
    float4* __restrict__ out)
{
    __shared__ float tcs[8], tss[8];                       // layer-0 half-angle trig
    __shared__ __align__(8) float dC[16], dI[16], dnI[16]; // fused RZ diagonal (packed layout)
    __shared__ float2 r0c[3], r1c[3], r2c[3];              // RY consts wires 0,1,2
    __shared__ float w3c[2];                               // cos(w3), -2 sin(w3)

    int tid = threadIdx.x;
    if (tid < 8) {
        float s, c; __sincosf(0.5f * w[tid], &s, &c);
        tcs[tid] = c; tss[tid] = s;
    } else if (tid >= 16 && tid < 32) {
        // diagonal: phi(k) = sum_q (w[8+2q]/2) * (-1)^par(k & m_q), m = {7,12,14,15}
        int k = tid - 16;
        float phi = 0.5f * ( w[8]  * ((__popc(k & 7)  & 1) ? -1.f : 1.f)
                           + w[10] * ((__popc(k & 12) & 1) ? -1.f : 1.f)
                           + w[12] * ((__popc(k & 14) & 1) ? -1.f : 1.f)
                           + w[14] * ((__popc(k & 15) & 1) ? -1.f : 1.f) );
        float sp, cp; __sincosf(phi, &sp, &cp);
        int pos = (k < 8) ? 2 * k : 2 * (k ^ 12) + 1;  // pack p = k or k^12, lane by k0
        dC[pos] = cp; dI[pos] = -sp; dnI[pos] = sp;    // e^{-i phi} = (cp, -sp)
    } else if (tid == 32) {       // wire0 RY, angle w[9]; in-pack cross-lane signs
        float s, c; __sincosf(0.5f * w[9], &s, &c);
        r0c[0] = make_float2(c, c); r0c[1] = make_float2(-s, s); r0c[2] = make_float2(s, -s);
    } else if (tid == 33) {       // wire1 RY, angle w[11]
        float s, c; __sincosf(0.5f * w[11], &s, &c);
        r1c[0] = make_float2(c, c); r1c[1] = make_float2(-s, -s); r1c[2] = make_float2(s, s);
    } else if (tid == 34) {       // wire2 RY, angle w[13]
        float s, c; __sincosf(0.5f * w[13], &s, &c);
        r2c[0] = make_float2(c, c); r2c[1] = make_float2(-s, -s); r2c[2] = make_float2(s, s);
    } else if (tid == 35) {       // wire3 RY fused into readout: full angle w[15]
        float s, c; __sincosf(w[15], &s, &c);
        w3c[0] = c; w3c[1] = -2.f * s;
    }
    __syncthreads();

    unsigned b = blockIdx.x * (unsigned)TPB + tid;
    float4 xv = x[b];
    float xs[4] = {xv.x, xv.y, xv.z, xv.w};

    // ---- product-state prologue: input RY + layer-0 RZ,RY on 2-vectors ----
    float2 u0[4], u1[4];
    #pragma unroll
    for (int q = 0; q < 4; q++) {
        float sx, cx;
        __sincosf(0.5f * xs[q], &sx, &cx);
        float cz = tcs[2 * q], sz = tss[2 * q];
        float cy = tcs[2 * q + 1], sy = tss[2 * q + 1];
        float2 v0 = make_float2(cx * cz, -cx * sz);
        float2 v1 = make_float2(sx * cz,  sx * sz);
        u0[q] = make_float2(fmaf(cy, v0.x, -sy * v1.x), fmaf(cy, v0.y, -sy * v1.y));
        u1[q] = make_float2(fmaf(sy, v0.x,  cy * v1.x), fmaf(sy, v0.y,  cy * v1.y));
    }
    float2 a01[4], a23[4];
    a01[0] = cmul(u0[0], u0[1]); a01[1] = cmul(u0[0], u1[1]);
    a01[2] = cmul(u1[0], u0[1]); a01[3] = cmul(u1[0], u1[1]);
    a23[0] = cmul(u0[2], u0[3]); a23[1] = cmul(u0[2], u1[3]);
    a23[2] = cmul(u1[2], u0[3]); a23[3] = cmul(u1[2], u1[3]);

    // ---- tensor product straight into packs along mask 12:
    //      pack p (p<8): lane0 = amp(k=p) = a01[p>>2]*a23[p&3], lane1 = amp(p^12) ----
    u64 A0R, A0I, A1R, A1I;
    F2PACK(A0R, a01[0].x, a01[3].x); F2PACK(A0I, a01[0].y, a01[3].y);
    F2PACK(A1R, a01[1].x, a01[2].x); F2PACK(A1I, a01[1].y, a01[2].y);
    u64 sR[8], sI[8];
    #pragma unroll
    for (int j = 0; j < 4; j++) {
        u64 BR, BI, nBI, t;
        F2PACK(BR, a23[j].x, a23[j].x);
        F2PACK(BI, a23[j].y, a23[j].y);
        float nb = -a23[j].y;
        F2PACK(nBI, nb, nb);
        F2MUL(t, A0R, BR); F2FMA(sR[j],     A0I, nBI, t);
        F2MUL(t, A0R, BI); F2FMA(sI[j],     A0I, BR,  t);
        F2MUL(t, A1R, BR); F2FMA(sR[4 + j], A1I, nBI, t);
        F2MUL(t, A1R, BI); F2FMA(sI[4 + j], A1I, BR,  t);
    }

    // ---- fused layer-1 RZ diagonal (all 4 qubits at once) ----
    {
        const u64* dCp  = reinterpret_cast<const u64*>(dC);
        const u64* dIp  = reinterpret_cast<const u64*>(dI);
        const u64* dnIp = reinterpret_cast<const u64*>(dnI);
        #pragma unroll
        for (int p = 0; p < 8; p++) {
            u64 cR = dCp[p], cI = dIp[p], ncI = dnIp[p];
            u64 t1, t2, oR = sR[p];
            F2MUL(t1, cR, sR[p]); F2MUL(t2, cR, sI[p]);
            F2FMA(sR[p], ncI, sI[p], t1);   // Re' = cR*Re - cI*Im
            F2FMA(sI[p], cI,  oR,    t2);   // Im' = cR*Im + cI*Re
        }
    }

    // ---- wire0 RY (pair mask 12 = in-pack cross-lane; role = par(p)) ----
    {
        const u64* rc = reinterpret_cast<const u64*>(r0c);
        u64 c0 = rc[0], svE = rc[1], svO = rc[2];
        #pragma unroll
        for (int p = 0; p < 8; p++) {
            u64 sv = (p == 0 || p == 3 || p == 5 || p == 6) ? svE : svO;
            u64 wR, wI, t1, t2;
            F2SWAP(wR, sR[p]); F2SWAP(wI, sI[p]);
            F2MUL(t1, c0, sR[p]); F2MUL(t2, c0, sI[p]);
            F2FMA(sR[p], sv, wR, t1);
            F2FMA(sI[p], sv, wI, t2);
        }
    }
    // ---- wire1 RY (pair mask 6): (A,B) pack pairs (0,6)(1,7)(2,4)(3,5) ----
    {
        const u64* rc = reinterpret_cast<const u64*>(r1c);
        u64 c = rc[0], sA = rc[1], sB = rc[2];
        ry_al(sR[0], sI[0], sR[6], sI[6], c, sA, sB);
        ry_al(sR[1], sI[1], sR[7], sI[7], c, sA, sB);
        ry_al(sR[2], sI[2], sR[4], sI[4], c, sA, sB);
        ry_al(sR[3], sI[3], sR[5], sI[5], c, sA, sB);
    }
    // ---- wire2 RY (pair mask 3): (A,B) pack pairs (0,3)(1,2)(7,4)(6,5) ----
    {
        const u64* rc = reinterpret_cast<const u64*>(r2c);
        u64 c = rc[0], sA = rc[1], sB = rc[2];
        ry_al(sR[0], sI[0], sR[3], sI[3], c, sA, sB);
        ry_al(sR[1], sI[1], sR[2], sI[2], c, sA, sB);
        ry_al(sR[7], sI[7], sR[4], sI[4], c, sA, sB);
        ry_al(sR[6], sI[6], sR[5], sI[5], c, sA, sB);
    }

    // ---- readout with wire3 RY fused ----
    // pre-RY3 probs per pack
    u64 P[8];
    #pragma unroll
    for (int p = 0; p < 8; p++) {
        u64 t; F2MUL(t, sR[p], sR[p]); F2FMA(P[p], sI[p], sI[p], t);
    }
    // cross terms Re(psi_k * conj(psi_{k^13})): pack pairs (0,1)(2,3)(4,5)(6,7), cross-lane
    u64 CR[4];
    #pragma unroll
    for (int i = 0; i < 4; i++) {
        int p = 2 * i;
        u64 wr, wi, t;
        F2SWAP(wr, sR[p + 1]); F2SWAP(wi, sI[p + 1]);
        F2MUL(t, sR[p], wr); F2FMA(CR[i], sI[p], wi, t);
    }
    u64 NEG1; F2PACK(NEG1, -1.0f, -1.0f);
    // butterflies over pack probs
    u64 sm[4], df[4];
    #pragma unroll
    for (int i = 0; i < 4; i++) {
        F2ADD(sm[i], P[2 * i], P[2 * i + 1]);
        F2FMA(df[i], P[2 * i + 1], NEG1, P[2 * i]);
    }
    u64 t1, t2, Ea, Eb, Ec, Up, Vd, g1, g2;
    F2ADD(t1, df[0], df[1]); F2ADD(t2, df[2], df[3]); F2FMA(Ea, t2, NEG1, t1); // sign par(p&5)
    F2ADD(t1, df[0], df[2]); F2ADD(t2, df[1], df[3]); F2FMA(Eb, t2, NEG1, t1); // sign par(p&3)
    F2ADD(t1, sm[0], sm[2]); F2ADD(t2, sm[1], sm[3]); F2FMA(Ec, t2, NEG1, t1); // sign par(p&2)
    F2FMA(g1, CR[1], NEG1, CR[0]); F2FMA(g2, CR[3], NEG1, CR[2]); F2ADD(Up, g1, g2);
    F2ADD(t1, CR[0], CR[1]); F2ADD(t2, CR[2], CR[3]); F2FMA(Vd, t2, NEG1, t1);

    float eal, eah, ebl, ebh, ecl, ech, upl, uph, vdl, vdh;
    F2UNPACK(eal, eah, Ea); F2UNPACK(ebl, ebh, Eb); F2UNPACK(ecl, ech, Ec);
    F2UNPACK(upl, uph, Up); F2UNPACK(vdl, vdh, Vd);
    float c3 = w3c[0], s3n2 = w3c[1];
    float W13 = eal + eah;   // <Z0> prob part (mask 13: lane-sum)
    float W5  = eal - eah;   // <Z2>           (mask 5 : lane-diff, same pack signs)
    float W11 = ebl - ebh;   // <Z1>           (mask 11)
    float W10 = ecl - ech;   // <Z3> prob part (mask 10)
    float C0 = upl + uph;    // cross sum for Z0
    float C3 = vdl - vdh;    // cross sum for Z3
    float4 o;
    o.x = fmaf(c3, W13, s3n2 * C0);
    o.y = W11;
    o.z = W5;
    o.w = fmaf(c3, W10, s3n2 * C3);
    out[b] = o;
}

extern "C" void kernel_launch(void* const* d_in, const int* in_sizes, int n_in,
                              void* d_out, int out_size) {
    const float4* x = (const float4*)d_in[0];
    const float*  w = (const float*)d_in[1];
    float4* out = (float4*)d_out;
    quantum_layer_kernel<<<BATCH / TPB, TPB>>>(x, w, out);
}

// round 6
// speedup vs baseline: 1.2759x; 1.0151x over previous
#include <cuda_runtime.h>

#define BATCH 524288u
#define TPB 256
#define GRID 740            // 148 SMs x 5 resident blocks @ 48 regs
typedef unsigned long long u64;

// ---- packed f32x2 primitives ----
#define F2MUL(d,a,b)    asm("mul.rn.f32x2 %0, %1, %2;" : "=l"(d) : "l"(a), "l"(b))
#define F2ADD(d,a,b)    asm("add.rn.f32x2 %0, %1, %2;" : "=l"(d) : "l"(a), "l"(b))
#define F2FMA(d,a,b,c)  asm("fma.rn.f32x2 %0, %1, %2, %3;" : "=l"(d) : "l"(a), "l"(b), "l"(c))
#define F2PACK(d,lo,hi) asm("mov.b64 %0, {%1, %2};" : "=l"(d) : "f"(lo), "f"(hi))
#define F2UNPACK(lo,hi,s) asm("mov.b64 {%0, %1}, %2;" : "=f"(lo), "=f"(hi) : "l"(s))
#define F2SWAP(d,s) asm("{\n\t.reg .b32 _l,_h;\n\tmov.b64 {_l,_h}, %1;\n\tmov.b64 %0, {_h,_l};\n\t}" : "=l"(d) : "l"(s))

__device__ __forceinline__ float2 cmul(float2 a, float2 b) {
    return make_float2(fmaf(a.x, b.x, -a.y * b.y), fmaf(a.x, b.y, a.y * b.x));
}

// lane-aligned RY on pack pair: A' = c*A + sA*B ; B' = c*B + sB*oldA
__device__ __forceinline__ void ry_al(u64& AR, u64& AI, u64& BR, u64& BI,
                                      u64 c2, u64 sA, u64 sB) {
    u64 t1, t2, t3, t4, oAR = AR, oAI = AI;
    F2MUL(t1, c2, AR); F2MUL(t2, c2, AI); F2MUL(t3, c2, BR); F2MUL(t4, c2, BI);
    F2FMA(AR, sA, BR, t1);
    F2FMA(AI, sA, BI, t2);
    F2FMA(BR, sB, oAR, t3);
    F2FMA(BI, sB, oAI, t4);
}

__global__ void __launch_bounds__(TPB, 5) quantum_layer_kernel(
    const float4* __restrict__ x, const float* __restrict__ w,
    float4* __restrict__ out)
{
    __shared__ float tcs[8], tss[8];                       // layer-0 half-angle trig
    __shared__ __align__(8) float dC[16], dI[16], dnI[16]; // fused RZ diagonal (packed layout)
    __shared__ float2 r0c[3], r1c[3], r2c[3];              // RY consts wires 0,1,2
    __shared__ float w3c[2];                               // cos(w3), -2 sin(w3)

    int tid = threadIdx.x;
    if (tid < 8) {
        float s, c; __sincosf(0.5f * w[tid], &s, &c);
        tcs[tid] = c; tss[tid] = s;
    } else if (tid >= 16 && tid < 32) {
        // diagonal: phi(k) = sum_q (w[8+2q]/2) * (-1)^par(k & m_q), m = {7,12,14,15}
        int k = tid - 16;
        float phi = 0.5f * ( w[8]  * ((__popc(k & 7)  & 1) ? -1.f : 1.f)
                           + w[10] * ((__popc(k & 12) & 1) ? -1.f : 1.f)
                           + w[12] * ((__popc(k & 14) & 1) ? -1.f : 1.f)
                           + w[14] * ((__popc(k & 15) & 1) ? -1.f : 1.f) );
        float sp, cp; __sincosf(phi, &sp, &cp);
        int pos = (k < 8) ? 2 * k : 2 * (k ^ 12) + 1;  // pack p = k or k^12, lane by k0
        dC[pos] = cp; dI[pos] = -sp; dnI[pos] = sp;    // e^{-i phi} = (cp, -sp)
    } else if (tid == 32) {       // wire0 RY, angle w[9]; in-pack cross-lane signs
        float s, c; __sincosf(0.5f * w[9], &s, &c);
        r0c[0] = make_float2(c, c); r0c[1] = make_float2(-s, s); r0c[2] = make_float2(s, -s);
    } else if (tid == 33) {       // wire1 RY, angle w[11]
        float s, c; __sincosf(0.5f * w[11], &s, &c);
        r1c[0] = make_float2(c, c); r1c[1] = make_float2(-s, -s); r1c[2] = make_float2(s, s);
    } else if (tid == 34) {       // wire2 RY, angle w[13]
        float s, c; __sincosf(0.5f * w[13], &s, &c);
        r2c[0] = make_float2(c, c); r2c[1] = make_float2(-s, -s); r2c[2] = make_float2(s, s);
    } else if (tid == 35) {       // wire3 RY fused into readout: full angle w[15]
        float s, c; __sincosf(w[15], &s, &c);
        w3c[0] = c; w3c[1] = -2.f * s;
    }
    __syncthreads();

    const u64* dCp  = reinterpret_cast<const u64*>(dC);
    const u64* dIp  = reinterpret_cast<const u64*>(dI);
    const u64* dnIp = reinterpret_cast<const u64*>(dnI);

    // ---- persistent grid-stride loop: one residency wave, 2-3 samples/thread ----
    for (unsigned b = blockIdx.x * (unsigned)TPB + tid; b < BATCH; b += GRID * TPB) {
        float4 xv = x[b];
        float xs[4] = {xv.x, xv.y, xv.z, xv.w};

        // ---- product-state prologue: input RY + layer-0 RZ,RY on 2-vectors ----
        float2 u0[4], u1[4];
        #pragma unroll
        for (int q = 0; q < 4; q++) {
            float sx, cx;
            __sincosf(0.5f * xs[q], &sx, &cx);
            float cz = tcs[2 * q], sz = tss[2 * q];
            float cy = tcs[2 * q + 1], sy = tss[2 * q + 1];
            float2 v0 = make_float2(cx * cz, -cx * sz);
            float2 v1 = make_float2(sx * cz,  sx * sz);
            u0[q] = make_float2(fmaf(cy, v0.x, -sy * v1.x), fmaf(cy, v0.y, -sy * v1.y));
            u1[q] = make_float2(fmaf(sy, v0.x,  cy * v1.x), fmaf(sy, v0.y,  cy * v1.y));
        }
        float2 a01[4], a23[4];
        a01[0] = cmul(u0[0], u0[1]); a01[1] = cmul(u0[0], u1[1]);
        a01[2] = cmul(u1[0], u0[1]); a01[3] = cmul(u1[0], u1[1]);
        a23[0] = cmul(u0[2], u0[3]); a23[1] = cmul(u0[2], u1[3]);
        a23[2] = cmul(u1[2], u0[3]); a23[3] = cmul(u1[2], u1[3]);

        // ---- tensor product straight into packs along mask 12:
        //      pack p (p<8): lane0 = amp(k=p), lane1 = amp(p^12) ----
        u64 A0R, A0I, A1R, A1I;
        F2PACK(A0R, a01[0].x, a01[3].x); F2PACK(A0I, a01[0].y, a01[3].y);
        F2PACK(A1R, a01[1].x, a01[2].x); F2PACK(A1I, a01[1].y, a01[2].y);
        u64 sR[8], sI[8];
        #pragma unroll
        for (int j = 0; j < 4; j++) {
            u64 BR, BI, nBI, t;
            F2PACK(BR, a23[j].x, a23[j].x);
            F2PACK(BI, a23[j].y, a23[j].y);
            float nb = -a23[j].y;
            F2PACK(nBI, nb, nb);
            F2MUL(t, A0R, BR); F2FMA(sR[j],     A0I, nBI, t);
            F2MUL(t, A0R, BI); F2FMA(sI[j],     A0I, BR,  t);
            F2MUL(t, A1R, BR); F2FMA(sR[4 + j], A1I, nBI, t);
            F2MUL(t, A1R, BI); F2FMA(sI[4 + j], A1I, BR,  t);
        }

        // ---- fused layer-1 RZ diagonal (all 4 qubits at once) ----
        #pragma unroll
        for (int p = 0; p < 8; p++) {
            u64 cR = dCp[p], cI = dIp[p], ncI = dnIp[p];
            u64 t1, t2, oR = sR[p];
            F2MUL(t1, cR, sR[p]); F2MUL(t2, cR, sI[p]);
            F2FMA(sR[p], ncI, sI[p], t1);   // Re' = cR*Re - cI*Im
            F2FMA(sI[p], cI,  oR,    t2);   // Im' = cR*Im + cI*Re
        }

        // ---- wire0 RY (pair mask 12 = in-pack cross-lane; role = par(p)) ----
        {
            const u64* rc = reinterpret_cast<const u64*>(r0c);
            u64 c0 = rc[0], svE = rc[1], svO = rc[2];
            #pragma unroll
            for (int p = 0; p < 8; p++) {
                u64 sv = (p == 0 || p == 3 || p == 5 || p == 6) ? svE : svO;
                u64 wR, wI, t1, t2;
                F2SWAP(wR, sR[p]); F2SWAP(wI, sI[p]);
                F2MUL(t1, c0, sR[p]); F2MUL(t2, c0, sI[p]);
                F2FMA(sR[p], sv, wR, t1);
                F2FMA(sI[p], sv, wI, t2);
            }
        }
        // ---- wire1 RY (pair mask 6): pack pairs (0,6)(1,7)(2,4)(3,5) ----
        {
            const u64* rc = reinterpret_cast<const u64*>(r1c);
            u64 c = rc[0], sA = rc[1], sB = rc[2];
            ry_al(sR[0], sI[0], sR[6], sI[6], c, sA, sB);
            ry_al(sR[1], sI[1], sR[7], sI[7], c, sA, sB);
            ry_al(sR[2], sI[2], sR[4], sI[4], c, sA, sB);
            ry_al(sR[3], sI[3], sR[5], sI[5], c, sA, sB);
        }
        // ---- wire2 RY (pair mask 3): pack pairs (0,3)(1,2)(7,4)(6,5) ----
        {
            const u64* rc = reinterpret_cast<const u64*>(r2c);
            u64 c = rc[0], sA = rc[1], sB = rc[2];
            ry_al(sR[0], sI[0], sR[3], sI[3], c, sA, sB);
            ry_al(sR[1], sI[1], sR[2], sI[2], c, sA, sB);
            ry_al(sR[7], sI[7], sR[4], sI[4], c, sA, sB);
            ry_al(sR[6], sI[6], sR[5], sI[5], c, sA, sB);
        }

        // ---- readout with wire3 RY fused ----
        u64 P[8];
        #pragma unroll
        for (int p = 0; p < 8; p++) {
            u64 t; F2MUL(t, sR[p], sR[p]); F2FMA(P[p], sI[p], sI[p], t);
        }
        // cross terms Re(psi_k * conj(psi_{k^13})): pack pairs (0,1)(2,3)(4,5)(6,7)
        u64 CR[4];
        #pragma unroll
        for (int i = 0; i < 4; i++) {
            int p = 2 * i;
            u64 wr, wi, t;
            F2SWAP(wr, sR[p + 1]); F2SWAP(wi, sI[p + 1]);
            F2MUL(t, sR[p], wr); F2FMA(CR[i], sI[p], wi, t);
        }
        u64 NEG1; F2PACK(NEG1, -1.0f, -1.0f);
        u64 sm[4], df[4];
        #pragma unroll
        for (int i = 0; i < 4; i++) {
            F2ADD(sm[i], P[2 * i], P[2 * i + 1]);
            F2FMA(df[i], P[2 * i + 1], NEG1, P[2 * i]);
        }
        u64 t1, t2, Ea, Eb, Ec, Up, Vd, g1, g2;
        F2ADD(t1, df[0], df[1]); F2ADD(t2, df[2], df[3]); F2FMA(Ea, t2, NEG1, t1); // par(p&5)
        F2ADD(t1, df[0], df[2]); F2ADD(t2, df[1], df[3]); F2FMA(Eb, t2, NEG1, t1); // par(p&3)
        F2ADD(t1, sm[0], sm[2]); F2ADD(t2, sm[1], sm[3]); F2FMA(Ec, t2, NEG1, t1); // par(p&2)
        F2FMA(g1, CR[1], NEG1, CR[0]); F2FMA(g2, CR[3], NEG1, CR[2]); F2ADD(Up, g1, g2);
        F2ADD(t1, CR[0], CR[1]); F2ADD(t2, CR[2], CR[3]); F2FMA(Vd, t2, NEG1, t1);

        float eal, eah, ebl, ebh, ecl, ech, upl, uph, vdl, vdh;
        F2UNPACK(eal, eah, Ea); F2UNPACK(ebl, ebh, Eb); F2UNPACK(ecl, ech, Ec);
        F2UNPACK(upl, uph, Up); F2UNPACK(vdl, vdh, Vd);
        float c3 = w3c[0], s3n2 = w3c[1];
        float W13 = eal + eah;   // <Z0> prob part (mask 13)
        float W5  = eal - eah;   // <Z2>           (mask 5)
        float W11 = ebl - ebh;   // <Z1>           (mask 11)
        float W10 = ecl - ech;   // <Z3> prob part (mask 10)
        float C0 = upl + uph;
        float C3 = vdl - vdh;
        float4 o;
        o.x = fmaf(c3, W13, s3n2 * C0);
        o.y = W11;
        o.z = W5;
        o.w = fmaf(c3, W10, s3n2 * C3);
        out[b] = o;
    }
}

extern "C" void kernel_launch(void* const* d_in, const int* in_sizes, int n_in,
                              void* d_out, int out_size) {
    const float4* x = (const float4*)d_in[0];
    const float*  w = (const float*)d_in[1];
    float4* out = (float4*)d_out;
    quantum_layer_kernel<<<GRID, TPB>>>(x, w, out);
}